// round 12
// baseline (speedup 1.0000x reference)
#include <cuda_runtime.h>
#include <cuda_fp16.h>
#include <cstdint>

// Problem constants
#define NB   64            // batch
#define CC   128           // channels
#define TT   300           // time
#define VV   25            // vertices
#define KK   3             // adjacency count
#define TV   (TT*VV)       // 7500 rows per n (r = t*25+w)
#define KD   (KK*CC)       // 384 = main GEMM K-dim
#define NELEM (NB*CC*TT*VV) // 61,440,000 output elems
#define BN_EPS 1e-5f
#define RPAD 7552          // padded rows per n for g_z (59*128)
#define KP 136             // padded k-dim of mgemm smem tiles (fp16)
#define XS 40              // zgemm sX row stride (fp16)
#define SS 136             // zgemm stage row stride (fp16)
#define MBLK 59            // mgemm row-blocks per n
#define NBLK2 (MBLK*NB)    // 3776 stats partials

typedef unsigned long long u64;

// ---------------- fp16 mma.sync + cp.async (base PTX, plain sm_103) ---------
__device__ __forceinline__ void mma16816(float* c, const uint32_t* a, const uint32_t* b) {
    asm volatile(
        "mma.sync.aligned.m16n8k16.row.col.f32.f16.f16.f32 "
        "{%0,%1,%2,%3}, {%4,%5,%6,%7}, {%8,%9}, {%0,%1,%2,%3};"
        : "+f"(c[0]), "+f"(c[1]), "+f"(c[2]), "+f"(c[3])
        : "r"(a[0]), "r"(a[1]), "r"(a[2]), "r"(a[3]), "r"(b[0]), "r"(b[1]));
}
__device__ __forceinline__ uint32_t smem_u32(const void* p) {
    uint32_t a;
    asm("{ .reg .u64 t; cvta.to.shared.u64 t, %1; cvt.u32.u64 %0, t; }"
        : "=r"(a) : "l"(p));
    return a;
}
__device__ __forceinline__ void cpa16(uint32_t s, const void* g) {
    asm volatile("cp.async.cg.shared.global [%0], [%1], 16;" :: "r"(s), "l"(g));
}
#define CP_COMMIT() asm volatile("cp.async.commit_group;" ::: "memory")
#define CP_WAIT(N)  asm volatile("cp.async.wait_group %0;" :: "n"(N) : "memory")

// ---------------- scratch ----------------------------------------------------
__device__ __half g_z[(size_t)NB * RPAD * KD];   // z[n][r][(k,ci)] fp16
__device__ __half g_W2[CC * KD];                 // W2[c][(k,ci)] fp16
__device__ float g_bias2[CC * VV];               // bias folded through A
__device__ float g_psum[NBLK2 * CC];
__device__ float g_psq[NBLK2 * CC];
__device__ float g_scale[CC];
__device__ float g_shift[CC];

// ---------------- kernel 0: prep (W2 fp16 permuted, fold bias) --------------
__global__ void prep_kernel(const float* __restrict__ W,
                            const float* __restrict__ b,
                            const float* __restrict__ A) {
    int tid = blockIdx.x * blockDim.x + threadIdx.x;
    int stride = gridDim.x * blockDim.x;
    for (int i = tid; i < CC * KD; i += stride) {
        int c = i / KD, rem = i - c * KD;
        int k = rem >> 7, ci = rem & 127;
        g_W2[i] = __float2half(W[(k * CC + c) * CC + ci]);
    }
    for (int i = tid; i < CC * VV; i += stride) {
        int c = i / VV, w = i % VV;
        float s = 0.f;
        #pragma unroll
        for (int k = 0; k < KK; k++) {
            float cs = 0.f;
            #pragma unroll
            for (int v = 0; v < VV; v++) cs += A[k * VV * VV + v * VV + w];
            s += b[k * CC + c] * cs;
        }
        g_bias2[i] = s;
    }
}

// ---------------- kernel 1: z-GEMM  z[n][t*25+w][k*128+ci] -------------------
// Per CTA: one n, 10 t. Per t: D[ci=128][(k,w)=75pad96] = X[ci][v pad32] *
// BA[(k,w)][v]. x(t+1) is prefetched into registers during the mma phase.
__global__ void __launch_bounds__(256) zgemm_kernel(const float* __restrict__ x,
                                                    const float* __restrict__ A) {
    __shared__ __half sX[128 * XS];       // [ci][v] padded
    __shared__ __half sBA[96 * XS];       // [(k*25+w)][v] padded, A transposed
    __shared__ __half stage[96 * SS];     // [(k,w)][ci]

    const int tb = blockIdx.x, n = blockIdx.y;
    const int tid = threadIdx.x;
    const int wid = tid >> 5, lane = tid & 31;
    const int wm = wid & 3, wn = wid >> 2;
    const int lr = lane >> 2, kq = (lane & 3) * 2;
    const float* xn0 = x + (size_t)(n * CC) * TV;

    for (int e = tid; e < 128 * XS; e += 256) sX[e] = __float2half(0.f);
    for (int e = tid; e < 96 * XS; e += 256) sBA[e] = __float2half(0.f);
    __syncthreads();
    for (int e = tid; e < KK * VV * VV; e += 256) {
        int k = e / (VV * VV), rem = e - k * VV * VV;
        int v = rem / VV, w = rem - v * VV;
        sBA[(k * VV + w) * XS + v] = __float2half(A[e]);
    }

    float rx[13];
    // preload t0 into regs, then sX
    {
        const float* xn = xn0 + (tb * 10) * VV;
        #pragma unroll
        for (int j = 0; j < 13; j++) {
            int e = tid + 256 * j;
            rx[j] = (e < CC * VV) ? xn[(size_t)(e / VV) * TV + e % VV] : 0.f;
        }
    }
    #pragma unroll
    for (int j = 0; j < 13; j++) {
        int e = tid + 256 * j;
        if (e < CC * VV) sX[(e / VV) * XS + e % VV] = __float2half(rx[j]);
    }
    __syncthreads();

    for (int tt = 0; tt < 10; tt++) {
        const int t = tb * 10 + tt;
        // prefetch x(t+1) into registers (LDGs in flight through mma phase)
        if (tt < 9) {
            const float* xn = xn0 + (t + 1) * VV;
            #pragma unroll
            for (int j = 0; j < 13; j++) {
                int e = tid + 256 * j;
                rx[j] = (e < CC * VV) ? xn[(size_t)(e / VV) * TV + e % VV] : 0.f;
            }
        }

        float acc[2][6][4];
        #pragma unroll
        for (int mt = 0; mt < 2; mt++)
            #pragma unroll
            for (int nt = 0; nt < 6; nt++)
                #pragma unroll
                for (int j = 0; j < 4; j++) acc[mt][nt][j] = 0.f;

        #pragma unroll
        for (int kk = 0; kk < 2; kk++) {
            const int k0 = kk * 16 + kq;
            uint32_t af[2][4], bf[6][2];
            #pragma unroll
            for (int mt = 0; mt < 2; mt++) {
                int rm = wm * 32 + mt * 16 + lr;
                af[mt][0] = *(const uint32_t*)(sX + rm * XS + k0);
                af[mt][1] = *(const uint32_t*)(sX + (rm + 8) * XS + k0);
                af[mt][2] = *(const uint32_t*)(sX + rm * XS + k0 + 8);
                af[mt][3] = *(const uint32_t*)(sX + (rm + 8) * XS + k0 + 8);
            }
            #pragma unroll
            for (int nt = 0; nt < 6; nt++) {
                int rn = wn * 48 + nt * 8 + lr;
                bf[nt][0] = *(const uint32_t*)(sBA + rn * XS + k0);
                bf[nt][1] = *(const uint32_t*)(sBA + rn * XS + k0 + 8);
            }
            #pragma unroll
            for (int mt = 0; mt < 2; mt++)
                #pragma unroll
                for (int nt = 0; nt < 6; nt++)
                    mma16816(acc[mt][nt], af[mt], bf[nt]);
        }

        // stage[(k,w)][ci] = D (fp16)
        #pragma unroll
        for (int mt = 0; mt < 2; mt++) {
            int row = wm * 32 + mt * 16 + lr;
            #pragma unroll
            for (int nt = 0; nt < 6; nt++) {
                int col = wn * 48 + nt * 8 + kq;
                stage[col * SS + row]           = __float2half(acc[mt][nt][0]);
                stage[(col + 1) * SS + row]     = __float2half(acc[mt][nt][1]);
                stage[col * SS + row + 8]       = __float2half(acc[mt][nt][2]);
                stage[(col + 1) * SS + row + 8] = __float2half(acc[mt][nt][3]);
            }
        }
        __syncthreads();          // stage complete; all mma reads of sX done

        // copy stage -> g_z ; refill sX for t+1 from registers
        __half* zb = g_z + ((size_t)n * RPAD + t * VV) * KD;
        for (int e = tid; e < 75 * 16; e += 256) {
            int q = e >> 4, h8 = (e & 15);
            int k = q / VV, w = q - k * VV;
            *(uint4*)(zb + (size_t)w * KD + k * CC + h8 * 8) =
                *(const uint4*)(stage + q * SS + h8 * 8);
        }
        if (tt < 9) {
            #pragma unroll
            for (int j = 0; j < 13; j++) {
                int e = tid + 256 * j;
                if (e < CC * VV) sX[(e / VV) * XS + e % VV] = __float2half(rx[j]);
            }
        }
        __syncthreads();          // copy + sX refill done before next mma
    }
}

// ---------------- kernel 2: main GEMM + bias + residual + relu + stats ------
// out[(n),(r)][c] = sum_kd z[n][r][kd] * W2[c][kd]; cp.async 2-stage on z.
#define SMEM_SA0 0
#define SMEM_SA1 34816
#define SMEM_SB  69632
#define SMEM_SCR 104448
#define SMEM_M_TOTAL (104448 + 2048)

__global__ void __launch_bounds__(256) mgemm_kernel(const float* __restrict__ x,
                                                    float* __restrict__ out) {
    extern __shared__ char sm[];
    __half* sAbuf[2] = { (__half*)(sm + SMEM_SA0), (__half*)(sm + SMEM_SA1) };
    __half* sB = (__half*)(sm + SMEM_SB);       // [128][KP]
    float* out_s = (float*)sm;                  // [128 c][130] epilogue alias
    float* scr = (float*)(sm + SMEM_SCR);       // 512 floats

    const int r0 = blockIdx.x * 128;
    const int n  = blockIdx.y;
    const int tid = threadIdx.x;
    const int wid = tid >> 5, lane = tid & 31;
    const int wm = wid & 1, wn = wid >> 1;
    const int lr = lane >> 2, kq = (lane & 3) * 2;
    const int arow = tid >> 4, ac8 = (tid & 15) * 8;   // per-thread A-copy coords

    const __half* srcAbase = g_z + ((size_t)n * RPAD + r0) * KD;

    // prologue: async-load sA chunk 0
    {
        uint32_t dst = smem_u32(sAbuf[0]) + (arow * KP + ac8) * 2;
        const __half* srcA = srcAbase;
        #pragma unroll
        for (int i = 0; i < 8; i++) {
            int row = arow + i * 16;
            cpa16(dst + i * 16 * KP * 2, srcA + (size_t)row * KD + ac8);
        }
    }
    CP_COMMIT();

    float acc[4][4][4];
    #pragma unroll
    for (int mt = 0; mt < 4; mt++)
        #pragma unroll
        for (int nt = 0; nt < 4; nt++)
            #pragma unroll
            for (int j = 0; j < 4; j++) acc[mt][nt][j] = 0.f;

    #pragma unroll
    for (int ch = 0; ch < 3; ch++) {
        // issue next chunk's sA async
        if (ch < 2) {
            uint32_t dst = smem_u32(sAbuf[(ch + 1) & 1]) + (arow * KP + ac8) * 2;
            const __half* srcA = srcAbase + (ch + 1) * CC;
            #pragma unroll
            for (int i = 0; i < 8; i++) {
                int row = arow + i * 16;
                cpa16(dst + i * 16 * KP * 2, srcA + (size_t)row * KD + ac8);
            }
            CP_COMMIT();
        }
        // blocking sB load (L2-hot W2)
        {
            const __half* srcB = g_W2 + ch * CC;
            #pragma unroll
            for (int i = 0; i < 8; i++) {
                int q = tid + 256 * i;
                int row = q >> 4, c8 = (q & 15) * 8;
                *(uint4*)(sB + row * KP + c8) = *(const uint4*)(srcB + (size_t)row * KD + c8);
            }
        }
        if (ch < 2) { CP_WAIT(1); } else { CP_WAIT(0); }
        __syncthreads();

        const __half* sA = sAbuf[ch & 1];
        #pragma unroll
        for (int kk = 0; kk < 8; kk++) {
            const int k0 = kk * 16 + kq;
            uint32_t af[4][4], bf[4][2];
            #pragma unroll
            for (int mt = 0; mt < 4; mt++) {
                int rm = wm * 64 + mt * 16 + lr;
                af[mt][0] = *(const uint32_t*)(sA + rm * KP + k0);
                af[mt][1] = *(const uint32_t*)(sA + (rm + 8) * KP + k0);
                af[mt][2] = *(const uint32_t*)(sA + rm * KP + k0 + 8);
                af[mt][3] = *(const uint32_t*)(sA + (rm + 8) * KP + k0 + 8);
            }
            #pragma unroll
            for (int nt = 0; nt < 4; nt++) {
                int rn = wn * 32 + nt * 8 + lr;
                bf[nt][0] = *(const uint32_t*)(sB + rn * KP + k0);
                bf[nt][1] = *(const uint32_t*)(sB + rn * KP + k0 + 8);
            }
            #pragma unroll
            for (int mt = 0; mt < 4; mt++)
                #pragma unroll
                for (int nt = 0; nt < 4; nt++)
                    mma16816(acc[mt][nt], af[mt], bf[nt]);
        }
        __syncthreads();   // done reading sB (and sA buffer not refilled until next iter's issue)
    }

    // stage D: out_s[c][r_loc]  (aliases sA region)
    #pragma unroll
    for (int mt = 0; mt < 4; mt++) {
        int r_loc = wm * 64 + mt * 16 + lr;
        #pragma unroll
        for (int nt = 0; nt < 4; nt++) {
            int cb = wn * 32 + nt * 8 + kq;
            out_s[cb * 130 + r_loc]           = acc[mt][nt][0];
            out_s[(cb + 1) * 130 + r_loc]     = acc[mt][nt][1];
            out_s[cb * 130 + r_loc + 8]       = acc[mt][nt][2];
            out_s[(cb + 1) * 130 + r_loc + 8] = acc[mt][nt][3];
        }
    }
    __syncthreads();

    // Phase A: bias + residual + relu; write out; keep in smem for stats
    for (int e = tid; e < 128 * 128; e += 256) {
        int c = e >> 7, r = e & 127;
        int gr = r0 + r;
        if (gr < TV) {
            size_t gidx = (size_t)(n * CC + c) * TV + gr;
            float v = out_s[c * 130 + r] + g_bias2[c * VV + gr % VV] + x[gidx];
            v = fmaxf(v, 0.f);
            out_s[c * 130 + r] = v;
            out[gidx] = v;
        }
    }
    __syncthreads();

    // Phase B: per-channel stats partials
    const int cc = tid & 127, th = tid >> 7;
    const int rmax = (TV - r0 < 128) ? (TV - r0) : 128;
    float bs = 0.f, bq = 0.f;
    for (int r = th; r < rmax; r += 2) {
        float v = out_s[cc * 130 + r];
        bs += v; bq += v * v;
    }
    scr[tid] = bs; scr[256 + tid] = bq;
    __syncthreads();
    if (th == 0) {
        int p = (n * MBLK + blockIdx.x) * CC + cc;
        g_psum[p] = scr[cc] + scr[cc + 128];
        g_psq[p]  = scr[256 + cc] + scr[256 + cc + 128];
    }
}

// ---------------- kernel 3: reduce partials, fold BN into scale/shift ------
__global__ void __launch_bounds__(256) stats_kernel(const float* __restrict__ gamma,
                                                    const float* __restrict__ beta) {
    const int c = blockIdx.x;
    const int tid = threadIdx.x;
    __shared__ float s1[256], s2[256];
    float a = 0.f, b2 = 0.f;
    for (int i = tid; i < NBLK2; i += 256) {
        a += g_psum[i * CC + c];
        b2 += g_psq[i * CC + c];
    }
    s1[tid] = a; s2[tid] = b2;
    __syncthreads();
    for (int s = 128; s > 0; s >>= 1) {
        if (tid < s) { s1[tid] += s1[tid + s]; s2[tid] += s2[tid + s]; }
        __syncthreads();
    }
    if (tid == 0) {
        const float inv = 1.f / (float)(NB * TT * VV);
        float mean = s1[0] * inv;
        float var = s2[0] * inv - mean * mean;
        float sc = gamma[c] * rsqrtf(var + BN_EPS);
        g_scale[c] = sc;
        g_shift[c] = beta[c] - mean * sc;
    }
}

// ---------------- kernel 4: in-place normalize + A passthrough tail --------
__global__ void normalize_kernel(float* __restrict__ out,
                                 const float* __restrict__ A,
                                 int out_size) {
    const int total4 = NELEM / 4;
    int stride = gridDim.x * blockDim.x;
    for (int idx = blockIdx.x * blockDim.x + threadIdx.x; idx < total4; idx += stride) {
        int e = idx * 4;
        int c = (e / TV) % CC;
        float sc = g_scale[c], sh = g_shift[c];
        float4 v = ((float4*)out)[idx];
        v.x = fmaf(v.x, sc, sh);
        v.y = fmaf(v.y, sc, sh);
        v.z = fmaf(v.z, sc, sh);
        v.w = fmaf(v.w, sc, sh);
        ((float4*)out)[idx] = v;
    }
    if (out_size > NELEM) {
        for (int j = blockIdx.x * blockDim.x + threadIdx.x;
             j < out_size - NELEM && j < KK * VV * VV; j += stride)
            out[NELEM + j] = A[j];
    }
}

// ---------------- launch ----------------------------------------------------
extern "C" void kernel_launch(void* const* d_in, const int* in_sizes, int n_in,
                              void* d_out, int out_size) {
    const float* x     = (const float*)d_in[0];
    const float* A     = (const float*)d_in[1];
    const float* W     = (const float*)d_in[2];
    const float* b     = (const float*)d_in[3];
    const float* gamma = (const float*)d_in[4];
    const float* beta  = (const float*)d_in[5];
    float* out = (float*)d_out;

    cudaFuncSetAttribute(mgemm_kernel,
                         cudaFuncAttributeMaxDynamicSharedMemorySize, SMEM_M_TOTAL);

    prep_kernel<<<64, 256>>>(W, b, A);

    dim3 gz(TT / 10, NB);                      // (30, 64)
    zgemm_kernel<<<gz, 256>>>(x, A);

    dim3 gm(MBLK, NB);                         // (59, 64)
    mgemm_kernel<<<gm, 256, SMEM_M_TOTAL>>>(x, out);

    stats_kernel<<<CC, 256>>>(gamma, beta);

    normalize_kernel<<<2048, 256>>>(out, A, out_size);
}

// round 13
// speedup vs baseline: 1.0870x; 1.0870x over previous
#include <cuda_runtime.h>
#include <cuda_fp16.h>
#include <cstdint>

// Problem constants
#define NB   64            // batch
#define CC   128           // channels
#define TT   300           // time
#define VV   25            // vertices
#define KK   3             // adjacency count
#define TV   (TT*VV)       // 7500 rows per n (r = t*25+w)
#define KD   (KK*CC)       // 384 = main GEMM K-dim
#define NELEM (NB*CC*TT*VV) // 61,440,000 output elems
#define BN_EPS 1e-5f
#define RPAD 7552          // padded rows per n for g_z (59*128)
#define KP 136             // padded k-dim of mgemm smem tiles (fp16)
#define XS 40              // zgemm row stride (fp16)
#define MBLK 59            // mgemm row-blocks per n
#define NBLK2 (MBLK*NB)    // 3776 stats partials

typedef unsigned long long u64;

// ---------------- fp16 mma.sync + cp.async (base PTX, plain sm_103) ---------
__device__ __forceinline__ void mma16816(float* c, const uint32_t* a, const uint32_t* b) {
    asm volatile(
        "mma.sync.aligned.m16n8k16.row.col.f32.f16.f16.f32 "
        "{%0,%1,%2,%3}, {%4,%5,%6,%7}, {%8,%9}, {%0,%1,%2,%3};"
        : "+f"(c[0]), "+f"(c[1]), "+f"(c[2]), "+f"(c[3])
        : "r"(a[0]), "r"(a[1]), "r"(a[2]), "r"(a[3]), "r"(b[0]), "r"(b[1]));
}
__device__ __forceinline__ uint32_t smem_u32(const void* p) {
    uint32_t a;
    asm("{ .reg .u64 t; cvta.to.shared.u64 t, %1; cvt.u32.u64 %0, t; }"
        : "=r"(a) : "l"(p));
    return a;
}
__device__ __forceinline__ void cpa16(uint32_t s, const void* g) {
    asm volatile("cp.async.cg.shared.global [%0], [%1], 16;" :: "r"(s), "l"(g));
}
__device__ __forceinline__ void cpa4(uint32_t s, const void* g) {
    asm volatile("cp.async.ca.shared.global [%0], [%1], 4;" :: "r"(s), "l"(g));
}
#define CP_COMMIT() asm volatile("cp.async.commit_group;" ::: "memory")
#define CP_WAIT0()  asm volatile("cp.async.wait_group 0;" ::: "memory")

// ---------------- scratch ----------------------------------------------------
__device__ __half g_z[(size_t)NB * RPAD * KD];   // z[n][r][(k,ci)] fp16
__device__ __half g_W2[CC * KD];                 // W2[c][(k,ci)] fp16
__device__ float g_bias2[CC * VV];               // bias folded through A
__device__ float g_psum[NBLK2 * CC];
__device__ float g_psq[NBLK2 * CC];
__device__ float g_scale[CC];
__device__ float g_shift[CC];

// ---------------- kernel 0: prep (W2 fp16 permuted, fold bias) --------------
__global__ void prep_kernel(const float* __restrict__ W,
                            const float* __restrict__ b,
                            const float* __restrict__ A) {
    int tid = blockIdx.x * blockDim.x + threadIdx.x;
    int stride = gridDim.x * blockDim.x;
    for (int i = tid; i < CC * KD; i += stride) {
        int c = i / KD, rem = i - c * KD;
        int k = rem >> 7, ci = rem & 127;
        g_W2[i] = __float2half(W[(k * CC + c) * CC + ci]);
    }
    for (int i = tid; i < CC * VV; i += stride) {
        int c = i / VV, w = i % VV;
        float s = 0.f;
        #pragma unroll
        for (int k = 0; k < KK; k++) {
            float cs = 0.f;
            #pragma unroll
            for (int v = 0; v < VV; v++) cs += A[k * VV * VV + v * VV + w];
            s += b[k * CC + c] * cs;
        }
        g_bias2[i] = s;
    }
}

// ---------------- kernel 1: z-GEMM  z[n][t*25+w][k*128+ci] -------------------
// D[(k,w)][ci] = sum_v BA[(k,w)][v] * X[ci][v]; fragments store DIRECTLY to
// g_z as __half2 (cols = adjacent ci). x(t+1) prefetched via cp.async into a
// double-buffered raw fp32 stage. 2 syncs/t, no stage tile.
__global__ void __launch_bounds__(256) zgemm_kernel(const float* __restrict__ x,
                                                    const float* __restrict__ A) {
    __shared__ float raw[2][CC * VV];     // 2 x 3200 fp32
    __shared__ __half sX[128 * XS];       // [ci][v] padded
    __shared__ __half sBA[96 * XS];       // [(k*25+w)][v] padded

    const int tb = blockIdx.x, n = blockIdx.y;
    const int tid = threadIdx.x;
    const int wid = tid >> 5, lane = tid & 31;
    const int wm = wid & 1, wn = wid >> 1;       // wm: 48-row half, wn: 32-ci group
    const int lr = lane >> 2, kq = (lane & 3) * 2;
    const float* xn0 = x + (size_t)(n * CC) * TV;

    for (int e = tid; e < 128 * XS; e += 256) sX[e] = __float2half(0.f);
    for (int e = tid; e < 96 * XS; e += 256) sBA[e] = __float2half(0.f);
    __syncthreads();
    for (int e = tid; e < KK * VV * VV; e += 256) {
        int k = e / (VV * VV), rem = e - k * VV * VV;
        int v = rem / VV, w = rem - v * VV;
        sBA[(k * VV + w) * XS + v] = __float2half(A[e]);
    }
    // prologue: async-load x(t0) raw, convert to sX
    {
        const float* xn = xn0 + (tb * 10) * VV;
        #pragma unroll
        for (int j = 0; j < 13; j++) {
            int e = tid + 256 * j;
            if (e < CC * VV) cpa4(smem_u32(&raw[0][e]), xn + (size_t)(e / VV) * TV + e % VV);
        }
        CP_COMMIT(); CP_WAIT0();
    }
    __syncthreads();
    #pragma unroll
    for (int j = 0; j < 13; j++) {
        int e = tid + 256 * j;
        if (e < CC * VV) sX[(e / VV) * XS + e % VV] = __float2half(raw[0][e]);
    }
    __syncthreads();

    for (int tt = 0; tt < 10; tt++) {
        const int t = tb * 10 + tt;
        // issue async prefetch of x(t+1)
        if (tt < 9) {
            const float* xn = xn0 + (t + 1) * VV;
            #pragma unroll
            for (int j = 0; j < 13; j++) {
                int e = tid + 256 * j;
                if (e < CC * VV)
                    cpa4(smem_u32(&raw[(tt + 1) & 1][e]), xn + (size_t)(e / VV) * TV + e % VV);
            }
            CP_COMMIT();
        }

        float acc[3][4][4];
        #pragma unroll
        for (int mt = 0; mt < 3; mt++)
            #pragma unroll
            for (int nt = 0; nt < 4; nt++)
                #pragma unroll
                for (int j = 0; j < 4; j++) acc[mt][nt][j] = 0.f;

        #pragma unroll
        for (int kk = 0; kk < 2; kk++) {
            const int k0 = kk * 16 + kq;
            uint32_t af[3][4], bf[4][2];
            #pragma unroll
            for (int mt = 0; mt < 3; mt++) {
                int q = wm * 48 + mt * 16 + lr;
                af[mt][0] = *(const uint32_t*)(sBA + q * XS + k0);
                af[mt][1] = *(const uint32_t*)(sBA + (q + 8) * XS + k0);
                af[mt][2] = *(const uint32_t*)(sBA + q * XS + k0 + 8);
                af[mt][3] = *(const uint32_t*)(sBA + (q + 8) * XS + k0 + 8);
            }
            #pragma unroll
            for (int nt = 0; nt < 4; nt++) {
                int ci = wn * 32 + nt * 8 + lr;
                bf[nt][0] = *(const uint32_t*)(sX + ci * XS + k0);
                bf[nt][1] = *(const uint32_t*)(sX + ci * XS + k0 + 8);
            }
            #pragma unroll
            for (int mt = 0; mt < 3; mt++)
                #pragma unroll
                for (int nt = 0; nt < 4; nt++)
                    mma16816(acc[mt][nt], af[mt], bf[nt]);
        }

        // direct fragment store: row q=(k*25+w) -> g_z[(t*25+w)*KD + k*128 + ci]
        __half* zb = g_z + ((size_t)n * RPAD + t * VV) * KD;
        #pragma unroll
        for (int mt = 0; mt < 3; mt++) {
            int q = wm * 48 + mt * 16 + lr;
            #pragma unroll
            for (int nt = 0; nt < 4; nt++) {
                int col = wn * 32 + nt * 8 + kq;
                if (q < 75) {
                    int k = q / VV, w = q - k * VV;
                    *(__half2*)(zb + (size_t)w * KD + k * CC + col) =
                        __floats2half2_rn(acc[mt][nt][0], acc[mt][nt][1]);
                }
                if (q + 8 < 75) {
                    int k = (q + 8) / VV, w = (q + 8) - k * VV;
                    *(__half2*)(zb + (size_t)w * KD + k * CC + col) =
                        __floats2half2_rn(acc[mt][nt][2], acc[mt][nt][3]);
                }
            }
        }

        if (tt < 9) CP_WAIT0();
        __syncthreads();           // mma reads of sX done; raw[(tt+1)&1] landed
        if (tt < 9) {
            #pragma unroll
            for (int j = 0; j < 13; j++) {
                int e = tid + 256 * j;
                if (e < CC * VV)
                    sX[(e / VV) * XS + e % VV] = __float2half(raw[(tt + 1) & 1][e]);
            }
        }
        __syncthreads();
    }
}

// ---------------- kernel 2: main GEMM + bias + residual + relu + stats ------
// out[(n),(r)][c] = sum_kd z[n][r][kd] * W2[c][kd]. R11 structure (2 CTA/SM),
// fills via cp.async (no register round-trip).
#define SMEM_M_TOTAL 69632

__global__ void __launch_bounds__(256) mgemm_kernel(const float* __restrict__ x,
                                                    float* __restrict__ out) {
    extern __shared__ char sm[];
    __half* sA = (__half*)sm;                   // [128][KP]
    __half* sB = (__half*)(sm + 34816);         // [128][KP]
    float* out_s = (float*)sm;                  // [128 c][130] epilogue alias
    float* scr = (float*)(sm + 66560);          // 512 floats

    const int r0 = blockIdx.x * 128;
    const int n  = blockIdx.y;
    const int tid = threadIdx.x;
    const int wid = tid >> 5, lane = tid & 31;
    const int wm = wid & 1, wn = wid >> 1;
    const int lr = lane >> 2, kq = (lane & 3) * 2;

    const __half* srcAbase = g_z + ((size_t)n * RPAD + r0) * KD;
    const uint32_t sAu = smem_u32(sA), sBu = smem_u32(sB);

    float acc[4][4][4];
    #pragma unroll
    for (int mt = 0; mt < 4; mt++)
        #pragma unroll
        for (int nt = 0; nt < 4; nt++)
            #pragma unroll
            for (int j = 0; j < 4; j++) acc[mt][nt][j] = 0.f;

    for (int ch = 0; ch < 3; ch++) {
        __syncthreads();
        {
            const __half* srcA = srcAbase + ch * CC;
            const __half* srcB = g_W2 + ch * CC;
            #pragma unroll
            for (int i = 0; i < 8; i++) {
                int q = tid + 256 * i;
                int row = q >> 4, c8 = (q & 15) * 8;
                cpa16(sAu + (row * KP + c8) * 2, srcA + (size_t)row * KD + c8);
                cpa16(sBu + (row * KP + c8) * 2, srcB + (size_t)row * KD + c8);
            }
            CP_COMMIT(); CP_WAIT0();
        }
        __syncthreads();

        #pragma unroll
        for (int kk = 0; kk < 8; kk++) {
            const int k0 = kk * 16 + kq;
            uint32_t af[4][4], bf[4][2];
            #pragma unroll
            for (int mt = 0; mt < 4; mt++) {
                int rm = wm * 64 + mt * 16 + lr;
                af[mt][0] = *(const uint32_t*)(sA + rm * KP + k0);
                af[mt][1] = *(const uint32_t*)(sA + (rm + 8) * KP + k0);
                af[mt][2] = *(const uint32_t*)(sA + rm * KP + k0 + 8);
                af[mt][3] = *(const uint32_t*)(sA + (rm + 8) * KP + k0 + 8);
            }
            #pragma unroll
            for (int nt = 0; nt < 4; nt++) {
                int rn = wn * 32 + nt * 8 + lr;
                bf[nt][0] = *(const uint32_t*)(sB + rn * KP + k0);
                bf[nt][1] = *(const uint32_t*)(sB + rn * KP + k0 + 8);
            }
            #pragma unroll
            for (int mt = 0; mt < 4; mt++)
                #pragma unroll
                for (int nt = 0; nt < 4; nt++)
                    mma16816(acc[mt][nt], af[mt], bf[nt]);
        }
    }
    __syncthreads();    // done with sA/sB; out_s aliases them

    // stage D: out_s[c][r_loc]
    #pragma unroll
    for (int mt = 0; mt < 4; mt++) {
        int r_loc = wm * 64 + mt * 16 + lr;
        #pragma unroll
        for (int nt = 0; nt < 4; nt++) {
            int cb = wn * 32 + nt * 8 + kq;
            out_s[cb * 130 + r_loc]           = acc[mt][nt][0];
            out_s[(cb + 1) * 130 + r_loc]     = acc[mt][nt][1];
            out_s[cb * 130 + r_loc + 8]       = acc[mt][nt][2];
            out_s[(cb + 1) * 130 + r_loc + 8] = acc[mt][nt][3];
        }
    }
    __syncthreads();

    // Phase A: bias + residual + relu; write out; keep in smem for stats
    for (int e = tid; e < 128 * 128; e += 256) {
        int c = e >> 7, r = e & 127;
        int gr = r0 + r;
        if (gr < TV) {
            size_t gidx = (size_t)(n * CC + c) * TV + gr;
            float v = out_s[c * 130 + r] + g_bias2[c * VV + gr % VV] + x[gidx];
            v = fmaxf(v, 0.f);
            out_s[c * 130 + r] = v;
            out[gidx] = v;
        }
    }
    __syncthreads();

    // Phase B: per-channel stats partials
    const int cc = tid & 127, th = tid >> 7;
    const int rmax = (TV - r0 < 128) ? (TV - r0) : 128;
    float bs = 0.f, bq = 0.f;
    for (int r = th; r < rmax; r += 2) {
        float v = out_s[cc * 130 + r];
        bs += v; bq += v * v;
    }
    scr[tid] = bs; scr[256 + tid] = bq;
    __syncthreads();
    if (th == 0) {
        int p = (n * MBLK + blockIdx.x) * CC + cc;
        g_psum[p] = scr[cc] + scr[cc + 128];
        g_psq[p]  = scr[256 + cc] + scr[256 + cc + 128];
    }
}

// ---------------- kernel 3: reduce partials, fold BN into scale/shift ------
__global__ void __launch_bounds__(256) stats_kernel(const float* __restrict__ gamma,
                                                    const float* __restrict__ beta) {
    const int c = blockIdx.x;
    const int tid = threadIdx.x;
    __shared__ float s1[256], s2[256];
    float a = 0.f, b2 = 0.f;
    for (int i = tid; i < NBLK2; i += 256) {
        a += g_psum[i * CC + c];
        b2 += g_psq[i * CC + c];
    }
    s1[tid] = a; s2[tid] = b2;
    __syncthreads();
    for (int s = 128; s > 0; s >>= 1) {
        if (tid < s) { s1[tid] += s1[tid + s]; s2[tid] += s2[tid + s]; }
        __syncthreads();
    }
    if (tid == 0) {
        const float inv = 1.f / (float)(NB * TT * VV);
        float mean = s1[0] * inv;
        float var = s2[0] * inv - mean * mean;
        float sc = gamma[c] * rsqrtf(var + BN_EPS);
        g_scale[c] = sc;
        g_shift[c] = beta[c] - mean * sc;
    }
}

// ---------------- kernel 4: in-place normalize + A passthrough tail --------
__global__ void normalize_kernel(float* __restrict__ out,
                                 const float* __restrict__ A,
                                 int out_size) {
    const int total4 = NELEM / 4;
    int stride = gridDim.x * blockDim.x;
    for (int idx = blockIdx.x * blockDim.x + threadIdx.x; idx < total4; idx += stride) {
        int e = idx * 4;
        int c = (e / TV) % CC;
        float sc = g_scale[c], sh = g_shift[c];
        float4 v = ((float4*)out)[idx];
        v.x = fmaf(v.x, sc, sh);
        v.y = fmaf(v.y, sc, sh);
        v.z = fmaf(v.z, sc, sh);
        v.w = fmaf(v.w, sc, sh);
        ((float4*)out)[idx] = v;
    }
    if (out_size > NELEM) {
        for (int j = blockIdx.x * blockDim.x + threadIdx.x;
             j < out_size - NELEM && j < KK * VV * VV; j += stride)
            out[NELEM + j] = A[j];
    }
}

// ---------------- launch ----------------------------------------------------
extern "C" void kernel_launch(void* const* d_in, const int* in_sizes, int n_in,
                              void* d_out, int out_size) {
    const float* x     = (const float*)d_in[0];
    const float* A     = (const float*)d_in[1];
    const float* W     = (const float*)d_in[2];
    const float* b     = (const float*)d_in[3];
    const float* gamma = (const float*)d_in[4];
    const float* beta  = (const float*)d_in[5];
    float* out = (float*)d_out;

    cudaFuncSetAttribute(mgemm_kernel,
                         cudaFuncAttributeMaxDynamicSharedMemorySize, SMEM_M_TOTAL);

    prep_kernel<<<64, 256>>>(W, b, A);

    dim3 gz(TT / 10, NB);                      // (30, 64)
    zgemm_kernel<<<gz, 256>>>(x, A);

    dim3 gm(MBLK, NB);                         // (59, 64)
    mgemm_kernel<<<gm, 256, SMEM_M_TOTAL>>>(x, out);

    stats_kernel<<<CC, 256>>>(gamma, beta);

    normalize_kernel<<<2048, 256>>>(out, A, out_size);
}

// round 14
// speedup vs baseline: 1.3674x; 1.2580x over previous
#include <cuda_runtime.h>
#include <cuda_fp16.h>
#include <cstdint>

// Problem constants
#define NB   64            // batch
#define CC   128           // channels
#define TT   300           // time
#define VV   25            // vertices
#define KK   3             // adjacency count
#define TV   (TT*VV)       // 7500 rows per n (r = t*25+w)
#define KD   (KK*CC)       // 384 = main GEMM K-dim
#define NELEM (NB*CC*TT*VV) // 61,440,000 output elems
#define BN_EPS 1e-5f
#define RPAD 7552          // padded rows per n for g_z (59*128)
#define KP 136             // padded k-dim of mgemm smem tiles (fp16)
#define XS 40              // zgemm sX row stride (fp16)
#define SS 136             // zgemm stage row stride (fp16)
#define MBLK 59            // mgemm row-blocks per n
#define NBLK2 (MBLK*NB)    // 3776 stats partials

typedef unsigned long long u64;

// ---------------- fp16 mma.sync + cp.async (base PTX, plain sm_103) ---------
__device__ __forceinline__ void mma16816(float* c, const uint32_t* a, const uint32_t* b) {
    asm volatile(
        "mma.sync.aligned.m16n8k16.row.col.f32.f16.f16.f32 "
        "{%0,%1,%2,%3}, {%4,%5,%6,%7}, {%8,%9}, {%0,%1,%2,%3};"
        : "+f"(c[0]), "+f"(c[1]), "+f"(c[2]), "+f"(c[3])
        : "r"(a[0]), "r"(a[1]), "r"(a[2]), "r"(a[3]), "r"(b[0]), "r"(b[1]));
}
__device__ __forceinline__ uint32_t smem_u32(const void* p) {
    uint32_t a;
    asm("{ .reg .u64 t; cvta.to.shared.u64 t, %1; cvt.u32.u64 %0, t; }"
        : "=r"(a) : "l"(p));
    return a;
}
__device__ __forceinline__ void cpa16(uint32_t s, const void* g) {
    asm volatile("cp.async.cg.shared.global [%0], [%1], 16;" :: "r"(s), "l"(g));
}
#define CP_COMMIT() asm volatile("cp.async.commit_group;" ::: "memory")
#define CP_WAIT0()  asm volatile("cp.async.wait_group 0;" ::: "memory")

// ---------------- scratch ----------------------------------------------------
__device__ __half g_z[(size_t)NB * RPAD * KD];   // z[n][r][(k,ci)] fp16
__device__ __half g_W2[CC * KD];                 // W2[c][(k,ci)] fp16
__device__ float g_bias2[CC * VV];               // bias folded through A
__device__ float g_psum[NBLK2 * CC];
__device__ float g_psq[NBLK2 * CC];
__device__ float g_scale[CC];
__device__ float g_shift[CC];

// ---------------- kernel -1: dummy (shifts ncu's profiled slot to mgemm) ----
__global__ void dummy_kernel() {}

// ---------------- kernel 0: prep (W2 fp16 permuted, fold bias) --------------
__global__ void prep_kernel(const float* __restrict__ W,
                            const float* __restrict__ b,
                            const float* __restrict__ A) {
    int tid = blockIdx.x * blockDim.x + threadIdx.x;
    int stride = gridDim.x * blockDim.x;
    for (int i = tid; i < CC * KD; i += stride) {
        int c = i / KD, rem = i - c * KD;
        int k = rem >> 7, ci = rem & 127;
        g_W2[i] = __float2half(W[(k * CC + c) * CC + ci]);
    }
    for (int i = tid; i < CC * VV; i += stride) {
        int c = i / VV, w = i % VV;
        float s = 0.f;
        #pragma unroll
        for (int k = 0; k < KK; k++) {
            float cs = 0.f;
            #pragma unroll
            for (int v = 0; v < VV; v++) cs += A[k * VV * VV + v * VV + w];
            s += b[k * CC + c] * cs;
        }
        g_bias2[i] = s;
    }
}

// ---------------- kernel 1: z-GEMM  z[n][t*25+w][k*128+ci] -------------------
// Per CTA: one n, 10 t. Per t: D[ci=128][(k,w)=75pad96] = X[ci][v pad32] *
// BA[(k,w)][v]. 2 syncs/t: the x(t+1) fill shares a barrier window with the
// stage->g_z copy so its LDG latency overlaps the copy stores.
__global__ void __launch_bounds__(256) zgemm_kernel(const float* __restrict__ x,
                                                    const float* __restrict__ A) {
    __shared__ __half sX[128 * XS];       // [ci][v] padded
    __shared__ __half sBA[96 * XS];       // [(k*25+w)][v] padded, A transposed
    __shared__ __half stage[96 * SS];     // [(k,w)][ci]

    const int tb = blockIdx.x, n = blockIdx.y;
    const int tid = threadIdx.x;
    const int wid = tid >> 5, lane = tid & 31;
    const int wm = wid & 3, wn = wid >> 2;
    const int lr = lane >> 2, kq = (lane & 3) * 2;
    const float* xn0 = x + (size_t)(n * CC) * TV;

    for (int e = tid; e < 128 * XS; e += 256) sX[e] = __float2half(0.f);
    for (int e = tid; e < 96 * XS; e += 256) sBA[e] = __float2half(0.f);
    __syncthreads();
    for (int e = tid; e < KK * VV * VV; e += 256) {
        int k = e / (VV * VV), rem = e - k * VV * VV;
        int v = rem / VV, w = rem - v * VV;
        sBA[(k * VV + w) * XS + v] = __float2half(A[e]);
    }
    // prologue: fill sX(t0)
    {
        const float* xn = xn0 + (tb * 10) * VV;
        for (int e = tid; e < CC * VV; e += 256)
            sX[(e / VV) * XS + e % VV] = __float2half(xn[(size_t)(e / VV) * TV + e % VV]);
    }
    __syncthreads();

    for (int tt = 0; tt < 10; tt++) {
        const int t = tb * 10 + tt;

        float acc[2][6][4];
        #pragma unroll
        for (int mt = 0; mt < 2; mt++)
            #pragma unroll
            for (int nt = 0; nt < 6; nt++)
                #pragma unroll
                for (int j = 0; j < 4; j++) acc[mt][nt][j] = 0.f;

        #pragma unroll
        for (int kk = 0; kk < 2; kk++) {
            const int k0 = kk * 16 + kq;
            uint32_t af[2][4], bf[6][2];
            #pragma unroll
            for (int mt = 0; mt < 2; mt++) {
                int rm = wm * 32 + mt * 16 + lr;
                af[mt][0] = *(const uint32_t*)(sX + rm * XS + k0);
                af[mt][1] = *(const uint32_t*)(sX + (rm + 8) * XS + k0);
                af[mt][2] = *(const uint32_t*)(sX + rm * XS + k0 + 8);
                af[mt][3] = *(const uint32_t*)(sX + (rm + 8) * XS + k0 + 8);
            }
            #pragma unroll
            for (int nt = 0; nt < 6; nt++) {
                int rn = wn * 48 + nt * 8 + lr;
                bf[nt][0] = *(const uint32_t*)(sBA + rn * XS + k0);
                bf[nt][1] = *(const uint32_t*)(sBA + rn * XS + k0 + 8);
            }
            #pragma unroll
            for (int mt = 0; mt < 2; mt++)
                #pragma unroll
                for (int nt = 0; nt < 6; nt++)
                    mma16816(acc[mt][nt], af[mt], bf[nt]);
        }

        // stage[(k,w)][ci] = D (fp16)
        #pragma unroll
        for (int mt = 0; mt < 2; mt++) {
            int row = wm * 32 + mt * 16 + lr;
            #pragma unroll
            for (int nt = 0; nt < 6; nt++) {
                int col = wn * 48 + nt * 8 + kq;
                stage[col * SS + row]           = __float2half(acc[mt][nt][0]);
                stage[(col + 1) * SS + row]     = __float2half(acc[mt][nt][1]);
                stage[col * SS + row + 8]       = __float2half(acc[mt][nt][2]);
                stage[(col + 1) * SS + row + 8] = __float2half(acc[mt][nt][3]);
            }
        }
        __syncthreads();          // stage complete; all mma reads of sX done

        // copy stage -> g_z  (coalesced uint4)  +  fill sX(t+1) in parallel
        __half* zb = g_z + ((size_t)n * RPAD + t * VV) * KD;
        for (int e = tid; e < 75 * 16; e += 256) {
            int q = e >> 4, h8 = (e & 15);
            int k = q / VV, w = q - k * VV;
            *(uint4*)(zb + (size_t)w * KD + k * CC + h8 * 8) =
                *(const uint4*)(stage + q * SS + h8 * 8);
        }
        if (tt < 9) {
            const float* xn = xn0 + (t + 1) * VV;
            for (int e = tid; e < CC * VV; e += 256)
                sX[(e / VV) * XS + e % VV] = __float2half(xn[(size_t)(e / VV) * TV + e % VV]);
        }
        __syncthreads();          // copy + refill done before next mma
    }
}

// ---------------- kernel 2: main GEMM + bias + residual + relu + stats ------
// out[(n),(r)][c] = sum_kd z[n][r][kd] * W2[c][kd]. R11 structure (2 CTA/SM),
// fills via cp.async.
#define SMEM_M_TOTAL 69632

__global__ void __launch_bounds__(256) mgemm_kernel(const float* __restrict__ x,
                                                    float* __restrict__ out) {
    extern __shared__ char sm[];
    __half* sA = (__half*)sm;                   // [128][KP]
    __half* sB = (__half*)(sm + 34816);         // [128][KP]
    float* out_s = (float*)sm;                  // [128 c][130] epilogue alias
    float* scr = (float*)(sm + 66560);          // 512 floats

    const int r0 = blockIdx.x * 128;
    const int n  = blockIdx.y;
    const int tid = threadIdx.x;
    const int wid = tid >> 5, lane = tid & 31;
    const int wm = wid & 1, wn = wid >> 1;
    const int lr = lane >> 2, kq = (lane & 3) * 2;

    const __half* srcAbase = g_z + ((size_t)n * RPAD + r0) * KD;
    const uint32_t sAu = smem_u32(sA), sBu = smem_u32(sB);

    float acc[4][4][4];
    #pragma unroll
    for (int mt = 0; mt < 4; mt++)
        #pragma unroll
        for (int nt = 0; nt < 4; nt++)
            #pragma unroll
            for (int j = 0; j < 4; j++) acc[mt][nt][j] = 0.f;

    for (int ch = 0; ch < 3; ch++) {
        __syncthreads();
        {
            const __half* srcA = srcAbase + ch * CC;
            const __half* srcB = g_W2 + ch * CC;
            #pragma unroll
            for (int i = 0; i < 8; i++) {
                int q = tid + 256 * i;
                int row = q >> 4, c8 = (q & 15) * 8;
                cpa16(sAu + (row * KP + c8) * 2, srcA + (size_t)row * KD + c8);
                cpa16(sBu + (row * KP + c8) * 2, srcB + (size_t)row * KD + c8);
            }
            CP_COMMIT(); CP_WAIT0();
        }
        __syncthreads();

        #pragma unroll
        for (int kk = 0; kk < 8; kk++) {
            const int k0 = kk * 16 + kq;
            uint32_t af[4][4], bf[4][2];
            #pragma unroll
            for (int mt = 0; mt < 4; mt++) {
                int rm = wm * 64 + mt * 16 + lr;
                af[mt][0] = *(const uint32_t*)(sA + rm * KP + k0);
                af[mt][1] = *(const uint32_t*)(sA + (rm + 8) * KP + k0);
                af[mt][2] = *(const uint32_t*)(sA + rm * KP + k0 + 8);
                af[mt][3] = *(const uint32_t*)(sA + (rm + 8) * KP + k0 + 8);
            }
            #pragma unroll
            for (int nt = 0; nt < 4; nt++) {
                int rn = wn * 32 + nt * 8 + lr;
                bf[nt][0] = *(const uint32_t*)(sB + rn * KP + k0);
                bf[nt][1] = *(const uint32_t*)(sB + rn * KP + k0 + 8);
            }
            #pragma unroll
            for (int mt = 0; mt < 4; mt++)
                #pragma unroll
                for (int nt = 0; nt < 4; nt++)
                    mma16816(acc[mt][nt], af[mt], bf[nt]);
        }
    }
    __syncthreads();    // done with sA/sB; out_s aliases them

    // stage D: out_s[c][r_loc]
    #pragma unroll
    for (int mt = 0; mt < 4; mt++) {
        int r_loc = wm * 64 + mt * 16 + lr;
        #pragma unroll
        for (int nt = 0; nt < 4; nt++) {
            int cb = wn * 32 + nt * 8 + kq;
            out_s[cb * 130 + r_loc]           = acc[mt][nt][0];
            out_s[(cb + 1) * 130 + r_loc]     = acc[mt][nt][1];
            out_s[cb * 130 + r_loc + 8]       = acc[mt][nt][2];
            out_s[(cb + 1) * 130 + r_loc + 8] = acc[mt][nt][3];
        }
    }
    __syncthreads();

    // Phase A: bias + residual + relu; write out; keep in smem for stats
    for (int e = tid; e < 128 * 128; e += 256) {
        int c = e >> 7, r = e & 127;
        int gr = r0 + r;
        if (gr < TV) {
            size_t gidx = (size_t)(n * CC + c) * TV + gr;
            float v = out_s[c * 130 + r] + g_bias2[c * VV + gr % VV] + x[gidx];
            v = fmaxf(v, 0.f);
            out_s[c * 130 + r] = v;
            out[gidx] = v;
        }
    }
    __syncthreads();

    // Phase B: per-channel stats partials
    const int cc = tid & 127, th = tid >> 7;
    const int rmax = (TV - r0 < 128) ? (TV - r0) : 128;
    float bs = 0.f, bq = 0.f;
    for (int r = th; r < rmax; r += 2) {
        float v = out_s[cc * 130 + r];
        bs += v; bq += v * v;
    }
    scr[tid] = bs; scr[256 + tid] = bq;
    __syncthreads();
    if (th == 0) {
        int p = (n * MBLK + blockIdx.x) * CC + cc;
        g_psum[p] = scr[cc] + scr[cc + 128];
        g_psq[p]  = scr[256 + cc] + scr[256 + cc + 128];
    }
}

// ---------------- kernel 3: reduce partials, fold BN into scale/shift ------
__global__ void __launch_bounds__(256) stats_kernel(const float* __restrict__ gamma,
                                                    const float* __restrict__ beta) {
    const int c = blockIdx.x;
    const int tid = threadIdx.x;
    __shared__ float s1[256], s2[256];
    float a = 0.f, b2 = 0.f;
    for (int i = tid; i < NBLK2; i += 256) {
        a += g_psum[i * CC + c];
        b2 += g_psq[i * CC + c];
    }
    s1[tid] = a; s2[tid] = b2;
    __syncthreads();
    for (int s = 128; s > 0; s >>= 1) {
        if (tid < s) { s1[tid] += s1[tid + s]; s2[tid] += s2[tid + s]; }
        __syncthreads();
    }
    if (tid == 0) {
        const float inv = 1.f / (float)(NB * TT * VV);
        float mean = s1[0] * inv;
        float var = s2[0] * inv - mean * mean;
        float sc = gamma[c] * rsqrtf(var + BN_EPS);
        g_scale[c] = sc;
        g_shift[c] = beta[c] - mean * sc;
    }
}

// ---------------- kernel 4: in-place normalize + A passthrough tail --------
__global__ void normalize_kernel(float* __restrict__ out,
                                 const float* __restrict__ A,
                                 int out_size) {
    const int total4 = NELEM / 4;
    int stride = gridDim.x * blockDim.x;
    for (int idx = blockIdx.x * blockDim.x + threadIdx.x; idx < total4; idx += stride) {
        int e = idx * 4;
        int c = (e / TV) % CC;
        float sc = g_scale[c], sh = g_shift[c];
        float4 v = ((float4*)out)[idx];
        v.x = fmaf(v.x, sc, sh);
        v.y = fmaf(v.y, sc, sh);
        v.z = fmaf(v.z, sc, sh);
        v.w = fmaf(v.w, sc, sh);
        ((float4*)out)[idx] = v;
    }
    if (out_size > NELEM) {
        for (int j = blockIdx.x * blockDim.x + threadIdx.x;
             j < out_size - NELEM && j < KK * VV * VV; j += stride)
            out[NELEM + j] = A[j];
    }
}

// ---------------- launch ----------------------------------------------------
extern "C" void kernel_launch(void* const* d_in, const int* in_sizes, int n_in,
                              void* d_out, int out_size) {
    const float* x     = (const float*)d_in[0];
    const float* A     = (const float*)d_in[1];
    const float* W     = (const float*)d_in[2];
    const float* b     = (const float*)d_in[3];
    const float* gamma = (const float*)d_in[4];
    const float* beta  = (const float*)d_in[5];
    float* out = (float*)d_out;

    cudaFuncSetAttribute(mgemm_kernel,
                         cudaFuncAttributeMaxDynamicSharedMemorySize, SMEM_M_TOTAL);

    dummy_kernel<<<1, 32>>>();                 // shifts ncu slot 3 onto mgemm

    prep_kernel<<<64, 256>>>(W, b, A);

    dim3 gz(TT / 10, NB);                      // (30, 64)
    zgemm_kernel<<<gz, 256>>>(x, A);

    dim3 gm(MBLK, NB);                         // (59, 64)
    mgemm_kernel<<<gm, 256, SMEM_M_TOTAL>>>(x, out);

    stats_kernel<<<CC, 256>>>(gamma, beta);

    normalize_kernel<<<2048, 256>>>(out, A, out_size);
}